// round 2
// baseline (speedup 1.0000x reference)
#include <cuda_runtime.h>
#include <cuda_bf16.h>

#define N_NODES 100000
#define N_EDGES 1600000
#define D 128
#define N_CONVS 6

// ---------------- scratch (device globals; no runtime allocation) ----------
__device__ __align__(16) float g_buf0[(size_t)N_NODES * D];
__device__ __align__(16) float g_buf1[(size_t)N_NODES * D];
__device__ __align__(16) float g_mean[(size_t)N_NODES * D];
__device__ int   g_deg[N_NODES];
__device__ float g_deginv[N_NODES];
__device__ int   g_off[N_NODES + 1];
__device__ int   g_cur[N_NODES];
__device__ int   g_eid[N_EDGES];
__device__ int   g_src[N_EDGES];

// ---------------- graph preprocessing --------------------------------------
// NOTE: edge_index arrives as int32 (JAX x64 disabled downcasts int64->int32).
__global__ void k_zero() {
    int i = blockIdx.x * blockDim.x + threadIdx.x;
    if (i < N_NODES) { g_deg[i] = 0; g_cur[i] = 0; }
}

__global__ void k_hist(const int* __restrict__ ei) {
    int e = blockIdx.x * blockDim.x + threadIdx.x;
    if (e < N_EDGES) {
        int dst = ei[N_EDGES + e];
        if (dst >= 0 && dst < N_NODES) atomicAdd(&g_deg[dst], 1);
    }
}

// single-block exclusive scan of degrees -> offsets; also deg_inv
__global__ void k_scan() {
    __shared__ int sums[1024];
    const int CH = (N_NODES + 1023) / 1024;  // 98
    int t = threadIdx.x;
    int s0 = min(t * CH, N_NODES);
    int s1 = min(s0 + CH, N_NODES);
    int s = 0;
    for (int i = s0; i < s1; i++) s += g_deg[i];
    sums[t] = s;
    __syncthreads();
    for (int off = 1; off < 1024; off <<= 1) {
        int v = (t >= off) ? sums[t - off] : 0;
        __syncthreads();
        sums[t] += v;
        __syncthreads();
    }
    int base = (t > 0) ? sums[t - 1] : 0;
    for (int i = s0; i < s1; i++) {
        g_off[i] = base;
        int d = g_deg[i];
        base += d;
        g_deginv[i] = 1.0f / (float)max(d, 1);
    }
    if (t == 0) g_off[N_NODES] = sums[1023];
}

__global__ void k_fill(const int* __restrict__ ei) {
    int e = blockIdx.x * blockDim.x + threadIdx.x;
    if (e < N_EDGES) {
        int dst = ei[N_EDGES + e];
        if (dst >= 0 && dst < N_NODES) {
            int pos = atomicAdd(&g_cur[dst], 1);
            g_eid[g_off[dst] + pos] = e;
        }
    }
}

// deterministic order: insertion-sort each node's edge ids (avg degree ~16),
// then resolve to source node ids. Makes fp32 sums bit-stable across replays.
__global__ void k_sortsrc(const int* __restrict__ ei) {
    int n = blockIdx.x * blockDim.x + threadIdx.x;
    if (n >= N_NODES) return;
    int s = g_off[n], e = g_off[n + 1];
    for (int i = s + 1; i < e; i++) {
        int key = g_eid[i];
        int j = i - 1;
        while (j >= s && g_eid[j] > key) { g_eid[j + 1] = g_eid[j]; j--; }
        g_eid[j + 1] = key;
    }
    for (int i = s; i < e; i++) g_src[i] = ei[g_eid[i]];
}

// ---------------- per-layer: mean aggregation (warp per node) --------------
__global__ void k_agg(const float* __restrict__ x) {
    int w = (int)((blockIdx.x * blockDim.x + threadIdx.x) >> 5);
    if (w >= N_NODES) return;
    int lane = threadIdx.x & 31;
    int s = g_off[w], e = g_off[w + 1];
    float ax = 0.f, ay = 0.f, az = 0.f, aw = 0.f;
    for (int i = s; i < e; i++) {
        int src = g_src[i];
        float4 v = *(const float4*)(x + (size_t)src * D + lane * 4);
        ax += v.x; ay += v.y; az += v.z; aw += v.w;
    }
    float di = g_deginv[w];
    float4 o = make_float4(ax * di, ay * di, az * di, aw * di);
    *(float4*)(g_mean + (size_t)w * D + lane * 4) = o;
}

// ---------------- per-layer fused GEMM: relu(mean@Wl + x@Wr + b) -----------
// BM=128, BN=128, fused K=256 (k<128 -> mean/Wl, k>=128 -> x/Wr).
// 256 threads, each computes an 8x8 micro-tile.
#define BM 128
#define BN 128
#define BK 16
#define TM 8
#define TN 8

__global__ __launch_bounds__(256, 2) void k_gemm(
    const float* __restrict__ Ax,
    const float* __restrict__ Wl, const float* __restrict__ Wr,
    const float* __restrict__ bias, float* __restrict__ out)
{
    __shared__ float As[BK][BM];
    __shared__ float Bs[BK][BN];
    int tid = threadIdx.x;
    int tx = tid & 15;   // output col group
    int ty = tid >> 4;   // output row group
    int row0 = blockIdx.x * BM;

    float acc[TM][TN];
#pragma unroll
    for (int i = 0; i < TM; i++)
#pragma unroll
        for (int j = 0; j < TN; j++) acc[i][j] = 0.f;

    for (int kt = 0; kt < 256 / BK; kt++) {
        int kbase = kt * BK;
        const float* A = (kbase < 128) ? g_mean : Ax;
        const float* W = (kbase < 128) ? Wl : Wr;
        int klocal = kbase & 127;

        // A tile: 128 rows x 16 cols = 512 float4, 2 per thread; store transposed
#pragma unroll
        for (int l = 0; l < 2; l++) {
            int f4 = tid * 2 + l;
            int r  = f4 >> 2;
            int c4 = f4 & 3;
            int gr = row0 + r;
            float4 v = make_float4(0.f, 0.f, 0.f, 0.f);
            if (gr < N_NODES)
                v = *(const float4*)(A + (size_t)gr * D + klocal + c4 * 4);
            As[c4 * 4 + 0][r] = v.x;
            As[c4 * 4 + 1][r] = v.y;
            As[c4 * 4 + 2][r] = v.z;
            As[c4 * 4 + 3][r] = v.w;
        }
        // W tile: 16 rows x 128 cols = 512 float4, 2 per thread
#pragma unroll
        for (int l = 0; l < 2; l++) {
            int f4 = tid * 2 + l;
            int kr = f4 >> 5;
            int j4 = f4 & 31;
            float4 v = *(const float4*)(W + (size_t)(klocal + kr) * D + j4 * 4);
            *(float4*)&Bs[kr][j4 * 4] = v;
        }
        __syncthreads();

#pragma unroll
        for (int k = 0; k < BK; k++) {
            float a[TM], bb[TN];
#pragma unroll
            for (int i = 0; i < TM; i++) a[i] = As[k][ty * TM + i];
#pragma unroll
            for (int j = 0; j < TN; j++) bb[j] = Bs[k][tx * TN + j];
#pragma unroll
            for (int i = 0; i < TM; i++)
#pragma unroll
                for (int j = 0; j < TN; j++) acc[i][j] += a[i] * bb[j];
        }
        __syncthreads();
    }

    // epilogue: + bias, relu
    float bv[TN];
#pragma unroll
    for (int j = 0; j < TN; j++) bv[j] = bias[tx * TN + j];
#pragma unroll
    for (int i = 0; i < TM; i++) {
        int gr = row0 + ty * TM + i;
        if (gr < N_NODES) {
            float4 o0, o1;
            o0.x = fmaxf(acc[i][0] + bv[0], 0.f);
            o0.y = fmaxf(acc[i][1] + bv[1], 0.f);
            o0.z = fmaxf(acc[i][2] + bv[2], 0.f);
            o0.w = fmaxf(acc[i][3] + bv[3], 0.f);
            o1.x = fmaxf(acc[i][4] + bv[4], 0.f);
            o1.y = fmaxf(acc[i][5] + bv[5], 0.f);
            o1.z = fmaxf(acc[i][6] + bv[6], 0.f);
            o1.w = fmaxf(acc[i][7] + bv[7], 0.f);
            *(float4*)(out + (size_t)gr * D + tx * TN)     = o0;
            *(float4*)(out + (size_t)gr * D + tx * TN + 4) = o1;
        }
    }
}

// ---------------- final linear D -> 1 (warp per node) ----------------------
__global__ void k_final(const float* __restrict__ x,
                        const float* __restrict__ Wlin,
                        const float* __restrict__ blin,
                        float* __restrict__ out) {
    int w = (int)((blockIdx.x * blockDim.x + threadIdx.x) >> 5);
    if (w >= N_NODES) return;
    int lane = threadIdx.x & 31;
    float4 v  = *(const float4*)(x + (size_t)w * D + lane * 4);
    float4 wv = *(const float4*)(Wlin + lane * 4);
    float d = v.x * wv.x + v.y * wv.y + v.z * wv.z + v.w * wv.w;
#pragma unroll
    for (int off = 16; off > 0; off >>= 1)
        d += __shfl_xor_sync(0xFFFFFFFFu, d, off);
    if (lane == 0) out[w] = d + blin[0];
}

// ---------------- launch ----------------------------------------------------
extern "C" void kernel_launch(void* const* d_in, const int* in_sizes, int n_in,
                              void* d_out, int out_size) {
    const float* x    = (const float*)d_in[0];
    const int*   ei   = (const int*)d_in[1];      // int32 edge_index [2, N_EDGES]
    const float* Wl   = (const float*)d_in[2];
    const float* Wr   = (const float*)d_in[3];
    const float* b    = (const float*)d_in[4];
    const float* Wlin = (const float*)d_in[5];
    const float* blin = (const float*)d_in[6];
    float*       out  = (float*)d_out;

    float* buf0 = nullptr;
    float* buf1 = nullptr;
    cudaGetSymbolAddress((void**)&buf0, g_buf0);
    cudaGetSymbolAddress((void**)&buf1, g_buf1);

    // graph preprocessing (deterministic CSR)
    k_zero<<<(N_NODES + 255) / 256, 256>>>();
    k_hist<<<(N_EDGES + 255) / 256, 256>>>(ei);
    k_scan<<<1, 1024>>>();
    k_fill<<<(N_EDGES + 255) / 256, 256>>>(ei);
    k_sortsrc<<<(N_NODES + 255) / 256, 256>>>(ei);

    const float* cur = x;
    for (int i = 0; i < N_CONVS; i++) {
        k_agg<<<(N_NODES * 32 + 255) / 256, 256>>>(cur);
        float* o = (i & 1) ? buf1 : buf0;
        k_gemm<<<(N_NODES + BM - 1) / BM, 256>>>(
            cur, Wl + (size_t)i * D * D, Wr + (size_t)i * D * D,
            b + (size_t)i * D, o);
        cur = o;
    }
    k_final<<<(N_NODES * 32 + 255) / 256, 256>>>(cur, Wlin, blin, out);
}

// round 4
// speedup vs baseline: 1.4347x; 1.4347x over previous
#include <cuda_runtime.h>
#include <cuda_bf16.h>
#include <cstdint>

#define N_NODES 100000
#define N_EDGES 1600000
#define D 128
#define N_CONVS 6

// ---------------- scratch (device globals; no runtime allocation) ----------
__device__ __align__(16) float g_buf0[(size_t)N_NODES * D];
__device__ __align__(16) float g_buf1[(size_t)N_NODES * D];
__device__ __align__(16) float g_mean[(size_t)N_NODES * D];
__device__ int   g_deg[N_NODES];
__device__ float g_deginv[N_NODES];
__device__ int   g_off[N_NODES + 1];
__device__ int   g_cur[N_NODES];
__device__ int   g_eid[N_EDGES];
__device__ int   g_src[N_EDGES];
// bf16-split weight copies, plain [k][n] layout:
// index [(layer*2 + h)*128 + k]*128 + n, h: 0=Wl, 1=Wr
__device__ __align__(16) __nv_bfloat16 g_Bh[(size_t)N_CONVS * 2 * D * D];
__device__ __align__(16) __nv_bfloat16 g_Bl[(size_t)N_CONVS * 2 * D * D];

// ---------------- graph preprocessing (edge_index is int32) -----------------
__global__ void k_zero() {
    int i = blockIdx.x * blockDim.x + threadIdx.x;
    if (i < N_NODES) { g_deg[i] = 0; g_cur[i] = 0; }
}

__global__ void k_hist(const int* __restrict__ ei) {
    int e = blockIdx.x * blockDim.x + threadIdx.x;
    if (e < N_EDGES) {
        int dst = ei[N_EDGES + e];
        if (dst >= 0 && dst < N_NODES) atomicAdd(&g_deg[dst], 1);
    }
}

__global__ void k_scan() {
    __shared__ int sums[1024];
    const int CH = (N_NODES + 1023) / 1024;
    int t = threadIdx.x;
    int s0 = min(t * CH, N_NODES);
    int s1 = min(s0 + CH, N_NODES);
    int s = 0;
    for (int i = s0; i < s1; i++) s += g_deg[i];
    sums[t] = s;
    __syncthreads();
    for (int off = 1; off < 1024; off <<= 1) {
        int v = (t >= off) ? sums[t - off] : 0;
        __syncthreads();
        sums[t] += v;
        __syncthreads();
    }
    int base = (t > 0) ? sums[t - 1] : 0;
    for (int i = s0; i < s1; i++) {
        g_off[i] = base;
        int d = g_deg[i];
        base += d;
        g_deginv[i] = 1.0f / (float)max(d, 1);
    }
    if (t == 0) g_off[N_NODES] = sums[1023];
}

__global__ void k_fill(const int* __restrict__ ei) {
    int e = blockIdx.x * blockDim.x + threadIdx.x;
    if (e < N_EDGES) {
        int dst = ei[N_EDGES + e];
        if (dst >= 0 && dst < N_NODES) {
            int pos = atomicAdd(&g_cur[dst], 1);
            g_eid[g_off[dst] + pos] = e;
        }
    }
}

__global__ void k_sortsrc(const int* __restrict__ ei) {
    int n = blockIdx.x * blockDim.x + threadIdx.x;
    if (n >= N_NODES) return;
    int s = g_off[n], e = g_off[n + 1];
    for (int i = s + 1; i < e; i++) {
        int key = g_eid[i];
        int j = i - 1;
        while (j >= s && g_eid[j] > key) { g_eid[j + 1] = g_eid[j]; j--; }
        g_eid[j + 1] = key;
    }
    for (int i = s; i < e; i++) g_src[i] = ei[g_eid[i]];
}

// ---------------- weight prep: bf16 2-term split -----------------------------
__global__ void k_prepB(const float* __restrict__ Wl, const float* __restrict__ Wr) {
    int idx = blockIdx.x * blockDim.x + threadIdx.x;
    if (idx >= N_CONVS * 2 * D * D) return;
    int n = idx & 127;
    int k = (idx >> 7) & 127;
    int h = (idx >> 14) & 1;
    int l = idx >> 15;
    const float* W = (h ? Wr : Wl) + (size_t)l * D * D;
    float w = W[k * D + n];
    __nv_bfloat16 hi = __float2bfloat16_rn(w);
    __nv_bfloat16 lo = __float2bfloat16_rn(w - __bfloat162float(hi));
    size_t o = ((size_t)(l * 2 + h) * D + k) * D + n;
    g_Bh[o] = hi;
    g_Bl[o] = lo;
}

// ---------------- per-layer: mean aggregation (warp per node) ---------------
__global__ void k_agg(const float* __restrict__ x) {
    int w = (int)((blockIdx.x * blockDim.x + threadIdx.x) >> 5);
    if (w >= N_NODES) return;
    int lane = threadIdx.x & 31;
    int s = g_off[w], e = g_off[w + 1];
    float ax = 0.f, ay = 0.f, az = 0.f, aw = 0.f;
    for (int i = s; i < e; i++) {
        int src = g_src[i];
        float4 v = *(const float4*)(x + (size_t)src * D + lane * 4);
        ax += v.x; ay += v.y; az += v.z; aw += v.w;
    }
    float di = g_deginv[w];
    float4 o = make_float4(ax * di, ay * di, az * di, aw * di);
    *(float4*)(g_mean + (size_t)w * D + lane * 4) = o;
}

// ---------------- mma.sync GEMM: relu(mean@Wl + x@Wr + b) -------------------
// Block: 256 thr / 8 warps, tile 128x128, K=256 fused as 4 chunks of 64.
// bf16 2-term split (Ah*Bh + Ah*Bl + Al*Bh), fp32 accum.
// SMEM (halves): A tiles 128 rows x 72 (64 + 8 pad), B tiles 64 rows x 136.
#define A_STRIDE 72
#define B_STRIDE 136
#define SM_AH 0
#define SM_AL (128 * A_STRIDE)             // 9216 halves
#define SM_BH (2 * 128 * A_STRIDE)         // 18432
#define SM_BL (2 * 128 * A_STRIDE + 64 * B_STRIDE)
#define SMEM_HALVES (2 * 128 * A_STRIDE + 2 * 64 * B_STRIDE)  // 35840 halves = 71680 B

__device__ __forceinline__ uint32_t smem_u32(const void* p) {
    uint32_t a;
    asm("{ .reg .u64 t; cvta.to.shared.u64 t, %1; cvt.u32.u64 %0, t; }" : "=r"(a) : "l"(p));
    return a;
}

__device__ __forceinline__ void ldsm4(uint32_t* r, uint32_t addr) {
    asm volatile("ldmatrix.sync.aligned.m8n8.x4.shared.b16 {%0,%1,%2,%3}, [%4];"
        : "=r"(r[0]), "=r"(r[1]), "=r"(r[2]), "=r"(r[3]) : "r"(addr));
}
__device__ __forceinline__ void ldsm4t(uint32_t* r, uint32_t addr) {
    asm volatile("ldmatrix.sync.aligned.m8n8.x4.trans.shared.b16 {%0,%1,%2,%3}, [%4];"
        : "=r"(r[0]), "=r"(r[1]), "=r"(r[2]), "=r"(r[3]) : "r"(addr));
}
__device__ __forceinline__ void mma16816(float* c, const uint32_t* a, uint32_t b0, uint32_t b1) {
    asm volatile("mma.sync.aligned.m16n8k16.row.col.f32.bf16.bf16.f32 "
        "{%0,%1,%2,%3}, {%4,%5,%6,%7}, {%8,%9}, {%0,%1,%2,%3};"
        : "+f"(c[0]), "+f"(c[1]), "+f"(c[2]), "+f"(c[3])
        : "r"(a[0]), "r"(a[1]), "r"(a[2]), "r"(a[3]), "r"(b0), "r"(b1));
}

__global__ __launch_bounds__(256) void k_gemm_mma(
    const float* __restrict__ Ax, int layer,
    const float* __restrict__ bias, float* __restrict__ out)
{
    extern __shared__ __nv_bfloat16 smem[];
    uint32_t sb = smem_u32(smem);
    int tid = threadIdx.x;
    int wid = tid >> 5, lane = tid & 31;
    int row0 = blockIdx.x * 128;

    int m0 = (wid >> 1) * 32;   // warp row base within tile
    int n0 = (wid & 1) * 64;    // warp col base within tile

    // ldmatrix per-lane address components
    int quad = lane >> 3, rin = lane & 7;
    int dr = (quad & 1) * 8 + rin;
    int dc = (quad >> 1) * 8;

    float acc[2][8][4];
#pragma unroll
    for (int m = 0; m < 2; m++)
#pragma unroll
        for (int nt = 0; nt < 8; nt++)
#pragma unroll
            for (int q = 0; q < 4; q++) acc[m][nt][q] = 0.f;

    for (int chunk = 0; chunk < 4; chunk++) {
        int h = chunk >> 1;                    // 0: mean@Wl, 1: x@Wr
        int kof = (chunk & 1) * 64;            // k offset within 128
        const float* src = h ? Ax : (const float*)g_mean;
        const __nv_bfloat16* bh = g_Bh + ((size_t)(layer * 2 + h) * D + kof) * D;
        const __nv_bfloat16* bl = g_Bl + ((size_t)(layer * 2 + h) * D + kof) * D;

        __syncthreads();  // protect smem from previous chunk's readers

        // Load B tiles: 64 rows x 128 halves per split, vectorized uint4
        {
            const uint4* s4h = (const uint4*)bh;
            const uint4* s4l = (const uint4*)bl;
#pragma unroll
            for (int i = 0; i < 4; i++) {
                int u = tid + i * 256;          // 1024 uint4 per split
                int kr = u >> 4, nq = u & 15;   // row, 8-half group
                *(uint4*)((char*)smem + (SM_BH * 2) + kr * (B_STRIDE * 2) + nq * 16) = s4h[u];
                *(uint4*)((char*)smem + (SM_BL * 2) + kr * (B_STRIDE * 2) + nq * 16) = s4l[u];
            }
        }
        // Load + split A: 128 rows x 64 fp32
#pragma unroll
        for (int i = 0; i < 8; i++) {
            int f = tid + i * 256;              // 2048 float4
            int r = f >> 4, c = (f & 15) * 4;
            int gr = row0 + r;
            float4 v = (gr < N_NODES)
                ? *(const float4*)(src + (size_t)gr * D + kof + c)
                : make_float4(0.f, 0.f, 0.f, 0.f);
            __nv_bfloat162 h01, h23, l01, l23;
            h01.x = __float2bfloat16_rn(v.x);
            h01.y = __float2bfloat16_rn(v.y);
            h23.x = __float2bfloat16_rn(v.z);
            h23.y = __float2bfloat16_rn(v.w);
            l01.x = __float2bfloat16_rn(v.x - __bfloat162float(h01.x));
            l01.y = __float2bfloat16_rn(v.y - __bfloat162float(h01.y));
            l23.x = __float2bfloat16_rn(v.z - __bfloat162float(h23.x));
            l23.y = __float2bfloat16_rn(v.w - __bfloat162float(h23.y));
            int byo = r * (A_STRIDE * 2) + c * 2;
            *(uint32_t*)((char*)smem + byo)     = *(uint32_t*)&h01;
            *(uint32_t*)((char*)smem + byo + 4) = *(uint32_t*)&h23;
            *(uint32_t*)((char*)smem + (SM_AL * 2) + byo)     = *(uint32_t*)&l01;
            *(uint32_t*)((char*)smem + (SM_AL * 2) + byo + 4) = *(uint32_t*)&l23;
        }
        __syncthreads();

        // 4 k-steps of 16
#pragma unroll
        for (int ks = 0; ks < 4; ks++) {
            int k0 = ks * 16;
            uint32_t ah[2][4], al[2][4];
#pragma unroll
            for (int mt = 0; mt < 2; mt++) {
                uint32_t aoff = (uint32_t)((m0 + mt * 16 + dr) * (A_STRIDE * 2) + (k0 + dc) * 2);
                ldsm4(ah[mt], sb + aoff);
                ldsm4(al[mt], sb + (uint32_t)(SM_AL * 2) + aoff);
            }
#pragma unroll
            for (int j = 0; j < 4; j++) {       // each j covers two n-tiles
                uint32_t boff = (uint32_t)((k0 + dr) * (B_STRIDE * 2) + (n0 + j * 16 + dc) * 2);
                uint32_t bhf[4], blf[4];
                ldsm4t(bhf, sb + (uint32_t)(SM_BH * 2) + boff);
                ldsm4t(blf, sb + (uint32_t)(SM_BL * 2) + boff);
#pragma unroll
                for (int mt = 0; mt < 2; mt++) {
                    mma16816(acc[mt][2 * j],     ah[mt], bhf[0], bhf[1]);
                    mma16816(acc[mt][2 * j],     ah[mt], blf[0], blf[1]);
                    mma16816(acc[mt][2 * j],     al[mt], bhf[0], bhf[1]);
                    mma16816(acc[mt][2 * j + 1], ah[mt], bhf[2], bhf[3]);
                    mma16816(acc[mt][2 * j + 1], ah[mt], blf[2], blf[3]);
                    mma16816(acc[mt][2 * j + 1], al[mt], bhf[2], bhf[3]);
                }
            }
        }
    }

    // epilogue: + bias, relu, store. c0,c1 -> row g; c2,c3 -> row g+8
    int g = lane >> 2;
    int cq = (lane & 3) * 2;
#pragma unroll
    for (int mt = 0; mt < 2; mt++) {
        int ra = row0 + m0 + mt * 16 + g;
        int rb = ra + 8;
#pragma unroll
        for (int nt = 0; nt < 8; nt++) {
            int col = n0 + nt * 8 + cq;
            float b0 = bias[col], b1 = bias[col + 1];
            if (ra < N_NODES) {
                float2 o;
                o.x = fmaxf(acc[mt][nt][0] + b0, 0.f);
                o.y = fmaxf(acc[mt][nt][1] + b1, 0.f);
                *(float2*)(out + (size_t)ra * D + col) = o;
            }
            if (rb < N_NODES) {
                float2 o;
                o.x = fmaxf(acc[mt][nt][2] + b0, 0.f);
                o.y = fmaxf(acc[mt][nt][3] + b1, 0.f);
                *(float2*)(out + (size_t)rb * D + col) = o;
            }
        }
    }
}

// ---------------- final linear D -> 1 (warp per node) -----------------------
__global__ void k_final(const float* __restrict__ x,
                        const float* __restrict__ Wlin,
                        const float* __restrict__ blin,
                        float* __restrict__ out) {
    int w = (int)((blockIdx.x * blockDim.x + threadIdx.x) >> 5);
    if (w >= N_NODES) return;
    int lane = threadIdx.x & 31;
    float4 v  = *(const float4*)(x + (size_t)w * D + lane * 4);
    float4 wv = *(const float4*)(Wlin + lane * 4);
    float d = v.x * wv.x + v.y * wv.y + v.z * wv.z + v.w * wv.w;
#pragma unroll
    for (int off = 16; off > 0; off >>= 1)
        d += __shfl_xor_sync(0xFFFFFFFFu, d, off);
    if (lane == 0) out[w] = d + blin[0];
}

// ---------------- launch -----------------------------------------------------
extern "C" void kernel_launch(void* const* d_in, const int* in_sizes, int n_in,
                              void* d_out, int out_size) {
    const float* x    = (const float*)d_in[0];
    const int*   ei   = (const int*)d_in[1];
    const float* Wl   = (const float*)d_in[2];
    const float* Wr   = (const float*)d_in[3];
    const float* b    = (const float*)d_in[4];
    const float* Wlin = (const float*)d_in[5];
    const float* blin = (const float*)d_in[6];
    float*       out  = (float*)d_out;

    float* buf0 = nullptr;
    float* buf1 = nullptr;
    cudaGetSymbolAddress((void**)&buf0, g_buf0);
    cudaGetSymbolAddress((void**)&buf1, g_buf1);

    cudaFuncSetAttribute(k_gemm_mma, cudaFuncAttributeMaxDynamicSharedMemorySize,
                         SMEM_HALVES * 2);

    // graph preprocessing (deterministic CSR) + weight prep
    k_zero<<<(N_NODES + 255) / 256, 256>>>();
    k_hist<<<(N_EDGES + 255) / 256, 256>>>(ei);
    k_scan<<<1, 1024>>>();
    k_fill<<<(N_EDGES + 255) / 256, 256>>>(ei);
    k_sortsrc<<<(N_NODES + 255) / 256, 256>>>(ei);
    k_prepB<<<(N_CONVS * 2 * D * D + 255) / 256, 256>>>(Wl, Wr);

    const float* cur = x;
    for (int i = 0; i < N_CONVS; i++) {
        k_agg<<<(N_NODES * 32 + 255) / 256, 256>>>(cur);
        float* o = (i & 1) ? buf1 : buf0;
        k_gemm_mma<<<(N_NODES + 127) / 128, 256, SMEM_HALVES * 2>>>(
            cur, i, b + (size_t)i * D, o);
        cur = o;
    }
    k_final<<<(N_NODES * 32 + 255) / 256, 256>>>(cur, Wlin, blin, out);
}

// round 5
// speedup vs baseline: 1.6525x; 1.1518x over previous
#include <cuda_runtime.h>
#include <cuda_bf16.h>
#include <cstdint>

#define N_NODES 100000
#define N_EDGES 1600000
#define D 128
#define N_CONVS 6

// ---------------- scratch (device globals; no runtime allocation) ----------
__device__ __align__(16) float g_buf0[(size_t)N_NODES * D];
__device__ __align__(16) float g_buf1[(size_t)N_NODES * D];
__device__ __align__(16) float g_mean[(size_t)N_NODES * D];
__device__ int   g_deg[N_NODES];
__device__ float g_deginv[N_NODES];
__device__ int   g_off[N_NODES + 1];
__device__ int   g_cur[N_NODES];
__device__ int   g_eid[N_EDGES];
__device__ int   g_src[N_EDGES];
// bf16-split weight copies, plain [k][n] layout:
// index [(layer*2 + h)*128 + k]*128 + n, h: 0=Wl, 1=Wr
__device__ __align__(16) __nv_bfloat16 g_Bh[(size_t)N_CONVS * 2 * D * D];
__device__ __align__(16) __nv_bfloat16 g_Bl[(size_t)N_CONVS * 2 * D * D];

// ---------------- graph preprocessing (edge_index is int32) -----------------
__global__ void k_hist(const int* __restrict__ ei) {
    int e = blockIdx.x * blockDim.x + threadIdx.x;
    if (e < N_EDGES) {
        int dst = ei[N_EDGES + e];
        if (dst >= 0 && dst < N_NODES) atomicAdd(&g_deg[dst], 1);
    }
}

__global__ void k_scan() {
    __shared__ int sums[1024];
    const int CH = (N_NODES + 1023) / 1024;
    int t = threadIdx.x;
    int s0 = min(t * CH, N_NODES);
    int s1 = min(s0 + CH, N_NODES);
    int s = 0;
    for (int i = s0; i < s1; i++) s += g_deg[i];
    sums[t] = s;
    __syncthreads();
    for (int off = 1; off < 1024; off <<= 1) {
        int v = (t >= off) ? sums[t - off] : 0;
        __syncthreads();
        sums[t] += v;
        __syncthreads();
    }
    int base = (t > 0) ? sums[t - 1] : 0;
    for (int i = s0; i < s1; i++) {
        g_off[i] = base;
        int d = g_deg[i];
        base += d;
        g_deginv[i] = 1.0f / (float)max(d, 1);
    }
    if (t == 0) g_off[N_NODES] = sums[1023];
}

__global__ void k_fill(const int* __restrict__ ei) {
    int e = blockIdx.x * blockDim.x + threadIdx.x;
    if (e < N_EDGES) {
        int dst = ei[N_EDGES + e];
        if (dst >= 0 && dst < N_NODES) {
            int pos = atomicAdd(&g_cur[dst], 1);
            g_eid[g_off[dst] + pos] = e;
        }
    }
}

__global__ void k_sortsrc(const int* __restrict__ ei) {
    int n = blockIdx.x * blockDim.x + threadIdx.x;
    if (n >= N_NODES) return;
    int s = g_off[n], e = g_off[n + 1];
    for (int i = s + 1; i < e; i++) {
        int key = g_eid[i];
        int j = i - 1;
        while (j >= s && g_eid[j] > key) { g_eid[j + 1] = g_eid[j]; j--; }
        g_eid[j + 1] = key;
    }
    for (int i = s; i < e; i++) g_src[i] = ei[g_eid[i]];
}

// ---------------- weight prep: bf16 2-term split -----------------------------
__global__ void k_prepB(const float* __restrict__ Wl, const float* __restrict__ Wr) {
    int idx = blockIdx.x * blockDim.x + threadIdx.x;
    if (idx >= N_CONVS * 2 * D * D) return;
    int n = idx & 127;
    int k = (idx >> 7) & 127;
    int h = (idx >> 14) & 1;
    int l = idx >> 15;
    const float* W = (h ? Wr : Wl) + (size_t)l * D * D;
    float w = W[k * D + n];
    __nv_bfloat16 hi = __float2bfloat16_rn(w);
    __nv_bfloat16 lo = __float2bfloat16_rn(w - __bfloat162float(hi));
    size_t o = ((size_t)(l * 2 + h) * D + k) * D + n;
    g_Bh[o] = hi;
    g_Bl[o] = lo;
}

// ---------------- per-layer: mean aggregation (warp per node) ---------------
__global__ void k_agg(const float* __restrict__ x) {
    int w = (int)((blockIdx.x * blockDim.x + threadIdx.x) >> 5);
    if (w >= N_NODES) return;
    int lane = threadIdx.x & 31;
    int s = g_off[w], e = g_off[w + 1];
    float ax = 0.f, ay = 0.f, az = 0.f, aw = 0.f;
    int i = s;
    for (; i + 1 < e; i += 2) {
        int s0 = g_src[i], s1 = g_src[i + 1];
        float4 v0 = *(const float4*)(x + (size_t)s0 * D + lane * 4);
        float4 v1 = *(const float4*)(x + (size_t)s1 * D + lane * 4);
        ax += v0.x; ay += v0.y; az += v0.z; aw += v0.w;
        ax += v1.x; ay += v1.y; az += v1.z; aw += v1.w;
    }
    if (i < e) {
        float4 v = *(const float4*)(x + (size_t)g_src[i] * D + lane * 4);
        ax += v.x; ay += v.y; az += v.z; aw += v.w;
    }
    float di = g_deginv[w];
    float4 o = make_float4(ax * di, ay * di, az * di, aw * di);
    *(float4*)(g_mean + (size_t)w * D + lane * 4) = o;
}

// ---------------- mma.sync GEMM: relu(mean@Wl + x@Wr + b) -------------------
// Block: 256 thr / 8 warps, tile 128x128, K=256 fused as 4 chunks of 64.
// bf16 2-term split (Ah*Bh + Ah*Bl + Al*Bh), fp32 accum.
#define A_STRIDE 72
#define B_STRIDE 136
#define SM_AH 0
#define SM_AL (128 * A_STRIDE)
#define SM_BH (2 * 128 * A_STRIDE)
#define SM_BL (2 * 128 * A_STRIDE + 64 * B_STRIDE)
#define SMEM_HALVES (2 * 128 * A_STRIDE + 2 * 64 * B_STRIDE)  // 71680 B

__device__ __forceinline__ uint32_t smem_u32(const void* p) {
    uint32_t a;
    asm("{ .reg .u64 t; cvta.to.shared.u64 t, %1; cvt.u32.u64 %0, t; }" : "=r"(a) : "l"(p));
    return a;
}
__device__ __forceinline__ void cp16(uint32_t saddr, const void* g) {
    asm volatile("cp.async.cg.shared.global [%0], [%1], 16;" :: "r"(saddr), "l"(g));
}
#define CP_COMMIT() asm volatile("cp.async.commit_group;" ::: "memory")
#define CP_WAIT0()  asm volatile("cp.async.wait_group 0;" ::: "memory")

__device__ __forceinline__ void ldsm4(uint32_t* r, uint32_t addr) {
    asm volatile("ldmatrix.sync.aligned.m8n8.x4.shared.b16 {%0,%1,%2,%3}, [%4];"
        : "=r"(r[0]), "=r"(r[1]), "=r"(r[2]), "=r"(r[3]) : "r"(addr));
}
__device__ __forceinline__ void ldsm4t(uint32_t* r, uint32_t addr) {
    asm volatile("ldmatrix.sync.aligned.m8n8.x4.trans.shared.b16 {%0,%1,%2,%3}, [%4];"
        : "=r"(r[0]), "=r"(r[1]), "=r"(r[2]), "=r"(r[3]) : "r"(addr));
}
__device__ __forceinline__ void mma16816(float* c, const uint32_t* a, uint32_t b0, uint32_t b1) {
    asm volatile("mma.sync.aligned.m16n8k16.row.col.f32.bf16.bf16.f32 "
        "{%0,%1,%2,%3}, {%4,%5,%6,%7}, {%8,%9}, {%0,%1,%2,%3};"
        : "+f"(c[0]), "+f"(c[1]), "+f"(c[2]), "+f"(c[3])
        : "r"(a[0]), "r"(a[1]), "r"(a[2]), "r"(a[3]), "r"(b0), "r"(b1));
}

__global__ __launch_bounds__(256, 2) void k_gemm_mma(
    const float* __restrict__ Ax, int layer,
    const float* __restrict__ bias, float* __restrict__ out)
{
    extern __shared__ __nv_bfloat16 smem[];
    uint32_t sb = smem_u32(smem);
    int tid = threadIdx.x;
    int wid = tid >> 5, lane = tid & 31;
    int row0 = blockIdx.x * 128;

    int m0 = (wid >> 1) * 32;   // warp row base within tile
    int n0 = (wid & 1) * 64;    // warp col base within tile

    // ldmatrix per-lane address components
    int quad = lane >> 3, rin = lane & 7;
    int dr = (quad & 1) * 8 + rin;
    int dc = (quad >> 1) * 8;

    float acc[2][8][4];
#pragma unroll
    for (int m = 0; m < 2; m++)
#pragma unroll
        for (int nt = 0; nt < 8; nt++)
#pragma unroll
            for (int q = 0; q < 4; q++) acc[m][nt][q] = 0.f;

    for (int chunk = 0; chunk < 4; chunk++) {
        int h = chunk >> 1;                    // 0: mean@Wl, 1: x@Wr
        int kof = (chunk & 1) * 64;            // k offset within 128
        const float* src = h ? Ax : (const float*)g_mean;
        const __nv_bfloat16* bh = g_Bh + ((size_t)(layer * 2 + h) * D + kof) * D;
        const __nv_bfloat16* bl = g_Bl + ((size_t)(layer * 2 + h) * D + kof) * D;

        __syncthreads();  // protect smem from previous chunk's readers

        // B tiles via cp.async (in flight during A convert below)
#pragma unroll
        for (int i = 0; i < 4; i++) {
            int u = tid + i * 256;              // 1024 x 16B per split
            int kr = u >> 4, nq = u & 15;
            uint32_t so = (uint32_t)(kr * (B_STRIDE * 2) + nq * 16);
            cp16(sb + (uint32_t)(SM_BH * 2) + so, (const char*)bh + kr * 256 + nq * 16);
            cp16(sb + (uint32_t)(SM_BL * 2) + so, (const char*)bl + kr * 256 + nq * 16);
        }
        CP_COMMIT();

        // Load + split A: 128 rows x 64 fp32
#pragma unroll
        for (int i = 0; i < 8; i++) {
            int f = tid + i * 256;              // 2048 float4
            int r = f >> 4, c = (f & 15) * 4;
            int gr = row0 + r;
            float4 v = (gr < N_NODES)
                ? *(const float4*)(src + (size_t)gr * D + kof + c)
                : make_float4(0.f, 0.f, 0.f, 0.f);
            __nv_bfloat162 h01, h23, l01, l23;
            h01.x = __float2bfloat16_rn(v.x);
            h01.y = __float2bfloat16_rn(v.y);
            h23.x = __float2bfloat16_rn(v.z);
            h23.y = __float2bfloat16_rn(v.w);
            l01.x = __float2bfloat16_rn(v.x - __bfloat162float(h01.x));
            l01.y = __float2bfloat16_rn(v.y - __bfloat162float(h01.y));
            l23.x = __float2bfloat16_rn(v.z - __bfloat162float(h23.x));
            l23.y = __float2bfloat16_rn(v.w - __bfloat162float(h23.y));
            int byo = r * (A_STRIDE * 2) + c * 2;
            *(uint32_t*)((char*)smem + byo)     = *(uint32_t*)&h01;
            *(uint32_t*)((char*)smem + byo + 4) = *(uint32_t*)&h23;
            *(uint32_t*)((char*)smem + (SM_AL * 2) + byo)     = *(uint32_t*)&l01;
            *(uint32_t*)((char*)smem + (SM_AL * 2) + byo + 4) = *(uint32_t*)&l23;
        }
        CP_WAIT0();
        __syncthreads();

        // 4 k-steps of 16
#pragma unroll
        for (int ks = 0; ks < 4; ks++) {
            int k0 = ks * 16;
            uint32_t ah[2][4], al[2][4];
#pragma unroll
            for (int mt = 0; mt < 2; mt++) {
                uint32_t aoff = (uint32_t)((m0 + mt * 16 + dr) * (A_STRIDE * 2) + (k0 + dc) * 2);
                ldsm4(ah[mt], sb + aoff);
                ldsm4(al[mt], sb + (uint32_t)(SM_AL * 2) + aoff);
            }
#pragma unroll
            for (int j = 0; j < 4; j++) {       // each j covers two n-tiles
                uint32_t boff = (uint32_t)((k0 + dr) * (B_STRIDE * 2) + (n0 + j * 16 + dc) * 2);
                uint32_t bhf[4], blf[4];
                ldsm4t(bhf, sb + (uint32_t)(SM_BH * 2) + boff);
                ldsm4t(blf, sb + (uint32_t)(SM_BL * 2) + boff);
                // term-major issue order: dependency distance 4 per accumulator
                mma16816(acc[0][2 * j],     ah[0], bhf[0], bhf[1]);
                mma16816(acc[1][2 * j],     ah[1], bhf[0], bhf[1]);
                mma16816(acc[0][2 * j + 1], ah[0], bhf[2], bhf[3]);
                mma16816(acc[1][2 * j + 1], ah[1], bhf[2], bhf[3]);
                mma16816(acc[0][2 * j],     ah[0], blf[0], blf[1]);
                mma16816(acc[1][2 * j],     ah[1], blf[0], blf[1]);
                mma16816(acc[0][2 * j + 1], ah[0], blf[2], blf[3]);
                mma16816(acc[1][2 * j + 1], ah[1], blf[2], blf[3]);
                mma16816(acc[0][2 * j],     al[0], bhf[0], bhf[1]);
                mma16816(acc[1][2 * j],     al[1], bhf[0], bhf[1]);
                mma16816(acc[0][2 * j + 1], al[0], bhf[2], bhf[3]);
                mma16816(acc[1][2 * j + 1], al[1], bhf[2], bhf[3]);
            }
        }
    }

    // epilogue: + bias, relu, store. c0,c1 -> row g; c2,c3 -> row g+8
    int g = lane >> 2;
    int cq = (lane & 3) * 2;
#pragma unroll
    for (int mt = 0; mt < 2; mt++) {
        int ra = row0 + m0 + mt * 16 + g;
        int rb = ra + 8;
#pragma unroll
        for (int nt = 0; nt < 8; nt++) {
            int col = n0 + nt * 8 + cq;
            float b0 = bias[col], b1 = bias[col + 1];
            if (ra < N_NODES) {
                float2 o;
                o.x = fmaxf(acc[mt][nt][0] + b0, 0.f);
                o.y = fmaxf(acc[mt][nt][1] + b1, 0.f);
                *(float2*)(out + (size_t)ra * D + col) = o;
            }
            if (rb < N_NODES) {
                float2 o;
                o.x = fmaxf(acc[mt][nt][2] + b0, 0.f);
                o.y = fmaxf(acc[mt][nt][3] + b1, 0.f);
                *(float2*)(out + (size_t)rb * D + col) = o;
            }
        }
    }
}

// ---------------- final linear D -> 1 (warp per node) -----------------------
__global__ void k_final(const float* __restrict__ x,
                        const float* __restrict__ Wlin,
                        const float* __restrict__ blin,
                        float* __restrict__ out) {
    int w = (int)((blockIdx.x * blockDim.x + threadIdx.x) >> 5);
    if (w >= N_NODES) return;
    int lane = threadIdx.x & 31;
    float4 v  = *(const float4*)(x + (size_t)w * D + lane * 4);
    float4 wv = *(const float4*)(Wlin + lane * 4);
    float d = v.x * wv.x + v.y * wv.y + v.z * wv.z + v.w * wv.w;
#pragma unroll
    for (int off = 16; off > 0; off >>= 1)
        d += __shfl_xor_sync(0xFFFFFFFFu, d, off);
    if (lane == 0) out[w] = d + blin[0];
}

// ---------------- launch -----------------------------------------------------
extern "C" void kernel_launch(void* const* d_in, const int* in_sizes, int n_in,
                              void* d_out, int out_size) {
    const float* x    = (const float*)d_in[0];
    const int*   ei   = (const int*)d_in[1];
    const float* Wl   = (const float*)d_in[2];
    const float* Wr   = (const float*)d_in[3];
    const float* b    = (const float*)d_in[4];
    const float* Wlin = (const float*)d_in[5];
    const float* blin = (const float*)d_in[6];
    float*       out  = (float*)d_out;

    float* buf0 = nullptr;
    float* buf1 = nullptr;
    void*  degp = nullptr;
    void*  curp = nullptr;
    cudaGetSymbolAddress((void**)&buf0, g_buf0);
    cudaGetSymbolAddress((void**)&buf1, g_buf1);
    cudaGetSymbolAddress(&degp, g_deg);
    cudaGetSymbolAddress(&curp, g_cur);

    cudaFuncSetAttribute(k_gemm_mma, cudaFuncAttributeMaxDynamicSharedMemorySize,
                         SMEM_HALVES * 2);

    // graph preprocessing (deterministic CSR) + weight prep
    cudaMemsetAsync(degp, 0, N_NODES * sizeof(int));
    cudaMemsetAsync(curp, 0, N_NODES * sizeof(int));
    k_hist<<<(N_EDGES + 255) / 256, 256>>>(ei);
    k_scan<<<1, 1024>>>();
    k_fill<<<(N_EDGES + 255) / 256, 256>>>(ei);
    k_sortsrc<<<(N_NODES + 255) / 256, 256>>>(ei);
    k_prepB<<<(N_CONVS * 2 * D * D + 255) / 256, 256>>>(Wl, Wr);

    const float* cur = x;
    for (int i = 0; i < N_CONVS; i++) {
        k_agg<<<(N_NODES * 32 + 255) / 256, 256>>>(cur);
        float* o = (i & 1) ? buf1 : buf0;
        k_gemm_mma<<<(N_NODES + 127) / 128, 256, SMEM_HALVES * 2>>>(
            cur, i, b + (size_t)i * D, o);
        cur = o;
    }
    k_final<<<(N_NODES * 32 + 255) / 256, 256>>>(cur, Wlin, blin, out);
}